// round 8
// baseline (speedup 1.0000x reference)
#include <cuda_runtime.h>
#include <cuda_bf16.h>
#include <cstdint>
#include <math.h>

#define N_TOK 2048
#define DIM   1024
#define NEXP  16
#define HID   2048
#define OUTD  1024
#define TOPK  2
#define NPAIR (N_TOK*TOPK)

// ---------------- scratch ----------------------------------------------------
__device__ int   g_cnt[NEXP];
__device__ int   g_off[NEXP+1];
__device__ int   g_cur[NEXP];
__device__ int   g_tok[NPAIR];
__device__ float g_prob[NPAIR];
__device__ int   g_tidx[N_TOK*TOPK];
__device__ float g_tp[N_TOK*TOPK];
__device__ float g_h[(size_t)NPAIR*HID];   // 32 MB hidden activations

// ---------------- small kernels ----------------------------------------------
__global__ void init_kernel() {
    if (threadIdx.x < NEXP) g_cnt[threadIdx.x] = 0;
}

__global__ void router_kernel(const float* __restrict__ z,
                              const float* __restrict__ rw,
                              const float* __restrict__ rb) {
    int n    = blockIdx.x;
    int tid  = threadIdx.x;
    int warp = tid >> 5, lane = tid & 31;
    __shared__ float logits[NEXP];
    const float* zr = z + (size_t)n * DIM;
    for (int e = warp; e < NEXP; e += 4) {
        const float* wr = rw + (size_t)e * DIM;
        float s = 0.f;
        for (int d = lane; d < DIM; d += 32) s += zr[d] * wr[d];
        #pragma unroll
        for (int o = 16; o; o >>= 1) s += __shfl_xor_sync(0xffffffffu, s, o);
        if (lane == 0) logits[e] = s + rb[e];
    }
    __syncthreads();
    if (tid == 0) {
        int i0 = 0; float v0 = logits[0];
        for (int e = 1; e < NEXP; e++) if (logits[e] > v0) { v0 = logits[e]; i0 = e; }
        int i1 = -1; float v1 = -1e30f;
        for (int e = 0; e < NEXP; e++) if (e != i0 && logits[e] > v1) { v1 = logits[e]; i1 = e; }
        float e2 = expf(v1 - v0);
        float inv = 1.0f / (1.0f + e2);
        g_tidx[n*2+0] = i0; g_tidx[n*2+1] = i1;
        g_tp[n*2+0] = inv;  g_tp[n*2+1] = e2 * inv;
        atomicAdd(&g_cnt[i0], 1);
        atomicAdd(&g_cnt[i1], 1);
    }
}

__global__ void scan_kernel() {
    if (threadIdx.x == 0) {
        int acc = 0;
        for (int e = 0; e < NEXP; e++) { g_off[e] = acc; g_cur[e] = acc; acc += g_cnt[e]; }
        g_off[NEXP] = acc;
    }
}

__global__ void scatter_kernel() {
    int n = blockIdx.x * blockDim.x + threadIdx.x;
    if (n >= N_TOK) return;
    #pragma unroll
    for (int k = 0; k < TOPK; k++) {
        int e = g_tidx[n*2+k];
        int pos = atomicAdd(&g_cur[e], 1);
        g_tok[pos]  = n;
        g_prob[pos] = g_tp[n*2+k];
    }
}

// ---------------- split-bf16 helpers ------------------------------------------
__device__ __forceinline__ void split4(float4 v, uint2& hi, uint2& lo) {
    __nv_bfloat162 h01 = __floats2bfloat162_rn(v.x, v.y);
    __nv_bfloat162 h23 = __floats2bfloat162_rn(v.z, v.w);
    float rx = v.x - __bfloat162float(h01.x);
    float ry = v.y - __bfloat162float(h01.y);
    float rz = v.z - __bfloat162float(h23.x);
    float rw = v.w - __bfloat162float(h23.y);
    __nv_bfloat162 l01 = __floats2bfloat162_rn(rx, ry);
    __nv_bfloat162 l23 = __floats2bfloat162_rn(rz, rw);
    hi.x = *reinterpret_cast<uint32_t*>(&h01);
    hi.y = *reinterpret_cast<uint32_t*>(&h23);
    lo.x = *reinterpret_cast<uint32_t*>(&l01);
    lo.y = *reinterpret_cast<uint32_t*>(&l23);
}

__device__ __forceinline__ void mma16816(float* d, const uint32_t* a, const uint32_t* b) {
    asm volatile(
        "mma.sync.aligned.m16n8k16.row.col.f32.bf16.bf16.f32 "
        "{%0,%1,%2,%3}, {%4,%5,%6,%7}, {%8,%9}, {%0,%1,%2,%3};"
        : "+f"(d[0]), "+f"(d[1]), "+f"(d[2]), "+f"(d[3])
        : "r"(a[0]), "r"(a[1]), "r"(a[2]), "r"(a[3]), "r"(b[0]), "r"(b[1]));
}

// ---------------- grouped GEMM via mma.sync bf16 (split-2, occ=2) -------------
// CTA tile 128(M pairs) x 128(N), K chunk = 32. 256 threads = 8 warps (2x4).
// Warp tile 64x32: 4 m-frags (16) x 4 n-frags (8), m16n8k16.
#define KC 32
#define SA 40                 // bf16 element stride per smem row (80 B)

// MODE 0: A = z[g_tok[pos]], epilogue = bias+gelu -> g_h
// MODE 1: A = g_h[pos],      epilogue = prob*(acc+bias) atomicAdd -> out
template<int KDIM, int NDIM, int MODE>
__global__ __launch_bounds__(256, 2)
void moe_gemm(const float* __restrict__ Asrc, const float* __restrict__ Bw,
              const float* __restrict__ bias, float* __restrict__ outp)
{
    constexpr int NC = KDIM / KC;
    int e   = blockIdx.z;
    int cnt = g_cnt[e];
    int m0  = blockIdx.y * 128;
    if (m0 >= cnt) return;
    int off = g_off[e];
    int n0  = blockIdx.x * 128;
    int cntRem = cnt - m0;

    __shared__ __align__(16) uint16_t Ah[128 * SA];
    __shared__ __align__(16) uint16_t Al[128 * SA];
    __shared__ __align__(16) uint16_t Bh[128 * SA];
    __shared__ __align__(16) uint16_t Bl[128 * SA];

    int tid  = threadIdx.x;
    int wid  = tid >> 5, lane = tid & 31;
    int wm   = wid >> 2, wn = wid & 3;          // 2 x 4 warp grid
    int quad = lane >> 2, tq = lane & 3;

    // staging: 2 threads per row, 16 fp32 each
    int srow = tid >> 1;
    int scol = (tid & 1) * 16;
    int rclamp = srow < cntRem ? srow : (cntRem - 1);
    const float* arow;
    if (MODE == 0) {
        int tok = g_tok[off + m0 + rclamp];
        arow = Asrc + (size_t)tok * KDIM;
    } else {
        arow = g_h + (size_t)(off + m0 + rclamp) * KDIM;
    }
    const float* brow = Bw + ((size_t)e * NDIM + n0 + srow) * KDIM;

    float acc[4][4][4];
    #pragma unroll
    for (int i = 0; i < 4; i++)
        #pragma unroll
        for (int j = 0; j < 4; j++)
            #pragma unroll
            for (int q = 0; q < 4; q++) acc[i][j][q] = 0.f;

    for (int ch = 0; ch < NC; ch++) {
        // stage current chunk (convert fp32 -> bf16 hi/lo)
        const float* ap = arow + ch*KC + scol;
        const float* bp = brow + ch*KC + scol;
        #pragma unroll
        for (int q = 0; q < 4; q++) {
            float4 av = *(const float4*)(ap + q*4);
            float4 bv = *(const float4*)(bp + q*4);
            uint2 hi, lo;
            int idx = srow * SA + scol + q*4;
            split4(av, hi, lo);
            *(uint2*)&Ah[idx] = hi;  *(uint2*)&Al[idx] = lo;
            split4(bv, hi, lo);
            *(uint2*)&Bh[idx] = hi;  *(uint2*)&Bl[idx] = lo;
        }
        __syncthreads();
        // compute: 2 k16-steps
        #pragma unroll
        for (int ks = 0; ks < 2; ks++) {
            int kb = ks * 16 + tq * 2;
            uint32_t bH[4][2], bL[4][2];
            #pragma unroll
            for (int nj = 0; nj < 4; nj++) {
                int nr = (wn*32 + nj*8 + quad) * SA + kb;
                bH[nj][0] = *(const uint32_t*)&Bh[nr];
                bH[nj][1] = *(const uint32_t*)&Bh[nr + 8];
                bL[nj][0] = *(const uint32_t*)&Bl[nr];
                bL[nj][1] = *(const uint32_t*)&Bl[nr + 8];
            }
            #pragma unroll
            for (int fi = 0; fi < 4; fi++) {
                int r0 = (wm*64 + fi*16 + quad) * SA + kb;
                int r1 = r0 + 8 * SA;
                uint32_t aH[4], aL[4];
                aH[0] = *(const uint32_t*)&Ah[r0];
                aH[1] = *(const uint32_t*)&Ah[r1];
                aH[2] = *(const uint32_t*)&Ah[r0 + 8];
                aH[3] = *(const uint32_t*)&Ah[r1 + 8];
                aL[0] = *(const uint32_t*)&Al[r0];
                aL[1] = *(const uint32_t*)&Al[r1];
                aL[2] = *(const uint32_t*)&Al[r0 + 8];
                aL[3] = *(const uint32_t*)&Al[r1 + 8];
                // pass-major order: same-acc dependent MMAs are 4 issues apart
                #pragma unroll
                for (int nj = 0; nj < 4; nj++) mma16816(acc[fi][nj], aH, bH[nj]);
                #pragma unroll
                for (int nj = 0; nj < 4; nj++) mma16816(acc[fi][nj], aH, bL[nj]);
                #pragma unroll
                for (int nj = 0; nj < 4; nj++) mma16816(acc[fi][nj], aL, bH[nj]);
            }
        }
        __syncthreads();
    }

    // ---------------- epilogue ----------------
    #pragma unroll
    for (int fi = 0; fi < 4; fi++) {
        #pragma unroll
        for (int half = 0; half < 2; half++) {
            int rr = wm*64 + fi*16 + quad + half*8;
            if (rr >= cntRem) continue;
            int pos = off + m0 + rr;
            if (MODE == 0) {
                float* dst = g_h + (size_t)pos * NDIM + n0;
                const float* bp = bias + (size_t)e * NDIM + n0;
                #pragma unroll
                for (int nj = 0; nj < 4; nj++) {
                    int col = wn*32 + nj*8 + tq*2;
                    float x0 = acc[fi][nj][half*2+0] + bp[col];
                    float x1 = acc[fi][nj][half*2+1] + bp[col+1];
                    float2 o;
                    o.x = 0.5f * x0 * (1.0f + erff(x0 * 0.70710678118654752f));
                    o.y = 0.5f * x1 * (1.0f + erff(x1 * 0.70710678118654752f));
                    *(float2*)(dst + col) = o;
                }
            } else {
                int   tok = g_tok[pos];
                float p   = g_prob[pos];
                float* dst = outp + (size_t)tok * NDIM + n0;
                const float* bp = bias + (size_t)e * NDIM + n0;
                #pragma unroll
                for (int nj = 0; nj < 4; nj++) {
                    int col = wn*32 + nj*8 + tq*2;
                    atomicAdd(dst + col,     p * (acc[fi][nj][half*2+0] + bp[col]));
                    atomicAdd(dst + col + 1, p * (acc[fi][nj][half*2+1] + bp[col+1]));
                }
            }
        }
    }
}

// ---------------- launch ------------------------------------------------------
extern "C" void kernel_launch(void* const* d_in, const int* in_sizes, int n_in,
                              void* d_out, int out_size) {
    const float* z  = (const float*)d_in[0];
    const float* rw = (const float*)d_in[1];
    const float* rb = (const float*)d_in[2];
    const float* w1 = (const float*)d_in[3];
    const float* b1 = (const float*)d_in[4];
    const float* w2 = (const float*)d_in[5];
    const float* b2 = (const float*)d_in[6];
    float* out = (float*)d_out;

    init_kernel<<<1, 32>>>();
    router_kernel<<<N_TOK, 128>>>(z, rw, rb);
    scan_kernel<<<1, 32>>>();
    scatter_kernel<<<(N_TOK + 255) / 256, 256>>>();
    cudaMemsetAsync(out, 0, (size_t)N_TOK * OUTD * sizeof(float), 0);

    dim3 g1(HID / 128, (NPAIR + 127) / 128, NEXP);
    moe_gemm<DIM, HID, 0><<<g1, 256>>>(z, w1, b1, nullptr);
    dim3 g2(OUTD / 128, (NPAIR + 127) / 128, NEXP);
    moe_gemm<HID, OUTD, 1><<<g2, 256>>>(nullptr, w2, b2, out);
}

// round 9
// speedup vs baseline: 1.4109x; 1.4109x over previous
#include <cuda_runtime.h>
#include <cuda_bf16.h>
#include <cstdint>
#include <math.h>

#define N_TOK 2048
#define DIM   1024
#define NEXP  16
#define HID   2048
#define OUTD  1024
#define TOPK  2
#define NPAIR (N_TOK*TOPK)

// ---------------- scratch ----------------------------------------------------
__device__ int   g_cnt[NEXP];
__device__ int   g_off[NEXP+1];
__device__ int   g_cur[NEXP];
__device__ int   g_tok[NPAIR];
__device__ float g_prob[NPAIR];
__device__ int   g_tidx[N_TOK*TOPK];
__device__ float g_tp[N_TOK*TOPK];
__device__ float g_h[(size_t)NPAIR*HID];   // 32 MB hidden activations

// ---------------- small kernels ----------------------------------------------
__global__ void init_kernel() {
    if (threadIdx.x < NEXP) g_cnt[threadIdx.x] = 0;
}

__global__ void router_kernel(const float* __restrict__ z,
                              const float* __restrict__ rw,
                              const float* __restrict__ rb) {
    int n    = blockIdx.x;
    int tid  = threadIdx.x;
    int warp = tid >> 5, lane = tid & 31;
    __shared__ float logits[NEXP];
    const float* zr = z + (size_t)n * DIM;
    for (int e = warp; e < NEXP; e += 4) {
        const float* wr = rw + (size_t)e * DIM;
        float s = 0.f;
        for (int d = lane; d < DIM; d += 32) s += zr[d] * wr[d];
        #pragma unroll
        for (int o = 16; o; o >>= 1) s += __shfl_xor_sync(0xffffffffu, s, o);
        if (lane == 0) logits[e] = s + rb[e];
    }
    __syncthreads();
    if (tid == 0) {
        int i0 = 0; float v0 = logits[0];
        for (int e = 1; e < NEXP; e++) if (logits[e] > v0) { v0 = logits[e]; i0 = e; }
        int i1 = -1; float v1 = -1e30f;
        for (int e = 0; e < NEXP; e++) if (e != i0 && logits[e] > v1) { v1 = logits[e]; i1 = e; }
        float e2 = expf(v1 - v0);
        float inv = 1.0f / (1.0f + e2);
        g_tidx[n*2+0] = i0; g_tidx[n*2+1] = i1;
        g_tp[n*2+0] = inv;  g_tp[n*2+1] = e2 * inv;
        atomicAdd(&g_cnt[i0], 1);
        atomicAdd(&g_cnt[i1], 1);
    }
}

__global__ void scan_kernel() {
    if (threadIdx.x == 0) {
        int acc = 0;
        for (int e = 0; e < NEXP; e++) { g_off[e] = acc; g_cur[e] = acc; acc += g_cnt[e]; }
        g_off[NEXP] = acc;
    }
}

__global__ void scatter_kernel() {
    int n = blockIdx.x * blockDim.x + threadIdx.x;
    if (n >= N_TOK) return;
    #pragma unroll
    for (int k = 0; k < TOPK; k++) {
        int e = g_tidx[n*2+k];
        int pos = atomicAdd(&g_cur[e], 1);
        g_tok[pos]  = n;
        g_prob[pos] = g_tp[n*2+k];
    }
}

// ---------------- helpers -----------------------------------------------------
__device__ __forceinline__ uint32_t smem_u32(const void* p) {
    uint32_t a;
    asm("{ .reg .u64 t; cvta.to.shared.u64 t, %1; cvt.u32.u64 %0, t; }" : "=r"(a) : "l"(p));
    return a;
}

__device__ __forceinline__ void split4(float4 v, uint2& hi, uint2& lo) {
    __nv_bfloat162 h01 = __floats2bfloat162_rn(v.x, v.y);
    __nv_bfloat162 h23 = __floats2bfloat162_rn(v.z, v.w);
    float rx = v.x - __bfloat162float(h01.x);
    float ry = v.y - __bfloat162float(h01.y);
    float rz = v.z - __bfloat162float(h23.x);
    float rw = v.w - __bfloat162float(h23.y);
    __nv_bfloat162 l01 = __floats2bfloat162_rn(rx, ry);
    __nv_bfloat162 l23 = __floats2bfloat162_rn(rz, rw);
    hi.x = *reinterpret_cast<uint32_t*>(&h01);
    hi.y = *reinterpret_cast<uint32_t*>(&h23);
    lo.x = *reinterpret_cast<uint32_t*>(&l01);
    lo.y = *reinterpret_cast<uint32_t*>(&l23);
}

__device__ __forceinline__ void mma16816(float* d, const uint32_t* a, const uint32_t* b) {
    asm volatile(
        "mma.sync.aligned.m16n8k16.row.col.f32.bf16.bf16.f32 "
        "{%0,%1,%2,%3}, {%4,%5,%6,%7}, {%8,%9}, {%0,%1,%2,%3};"
        : "+f"(d[0]), "+f"(d[1]), "+f"(d[2]), "+f"(d[3])
        : "r"(a[0]), "r"(a[1]), "r"(a[2]), "r"(a[3]), "r"(b[0]), "r"(b[1]));
}

__device__ __forceinline__ void ldmx4(uint32_t& r0, uint32_t& r1, uint32_t& r2, uint32_t& r3,
                                      uint32_t addr) {
    asm volatile("ldmatrix.sync.aligned.m8n8.x4.shared.b16 {%0,%1,%2,%3}, [%4];"
                 : "=r"(r0), "=r"(r1), "=r"(r2), "=r"(r3) : "r"(addr));
}

// ---------------- grouped GEMM via mma.sync bf16 (split-2, ldmatrix) ----------
// CTA tile 128(M pairs) x 128(N), K chunk = 32. 256 threads = 8 warps (2x4).
// Warp tile 64x32: 4 m-frags (16) x 4 n-frags (8), m16n8k16.
#define KC 32
#define SA 40                 // bf16 element stride per smem row (80 B)

// MODE 0: A = z[g_tok[pos]], epilogue = bias+gelu -> g_h
// MODE 1: A = g_h[pos],      epilogue = prob*(acc+bias) atomicAdd -> out
template<int KDIM, int NDIM, int MODE>
__global__ __launch_bounds__(256, 1)
void moe_gemm(const float* __restrict__ Asrc, const float* __restrict__ Bw,
              const float* __restrict__ bias, float* __restrict__ outp)
{
    constexpr int NC = KDIM / KC;
    int e   = blockIdx.z;
    int cnt = g_cnt[e];
    int m0  = blockIdx.y * 128;
    if (m0 >= cnt) return;
    int off = g_off[e];
    int n0  = blockIdx.x * 128;
    int cntRem = cnt - m0;

    __shared__ __align__(16) uint16_t Ah[128 * SA];
    __shared__ __align__(16) uint16_t Al[128 * SA];
    __shared__ __align__(16) uint16_t Bh[128 * SA];
    __shared__ __align__(16) uint16_t Bl[128 * SA];

    int tid  = threadIdx.x;
    int wid  = tid >> 5, lane = tid & 31;
    int wm   = wid >> 2, wn = wid & 3;          // 2 x 4 warp grid
    int quad = lane >> 2, tq = lane & 3;

    uint32_t AhAddr = smem_u32(Ah), AlAddr = smem_u32(Al);
    uint32_t BhAddr = smem_u32(Bh), BlAddr = smem_u32(Bl);

    // ldmatrix per-lane row/col bases (element units)
    int a_row  = wm*64 + (lane & 15);
    int a_koff = (lane >> 4) * 8;
    int b_row  = wn*32 + (lane & 7) + ((lane >> 4) & 1) * 8;
    int b_koff = ((lane >> 3) & 1) * 8;

    // staging: 2 threads per row, 16 fp32 each
    int srow = tid >> 1;
    int scol = (tid & 1) * 16;
    int rclamp = srow < cntRem ? srow : (cntRem - 1);
    const float* arow;
    if (MODE == 0) {
        int tok = g_tok[off + m0 + rclamp];
        arow = Asrc + (size_t)tok * KDIM;
    } else {
        arow = g_h + (size_t)(off + m0 + rclamp) * KDIM;
    }
    const float* brow = Bw + ((size_t)e * NDIM + n0 + srow) * KDIM;

    float acc[4][4][4];
    #pragma unroll
    for (int i = 0; i < 4; i++)
        #pragma unroll
        for (int j = 0; j < 4; j++)
            #pragma unroll
            for (int q = 0; q < 4; q++) acc[i][j][q] = 0.f;

    float4 pa[4], pb[4];
    #pragma unroll
    for (int q = 0; q < 4; q++) {
        pa[q] = *(const float4*)(arow + scol + q*4);
        pb[q] = *(const float4*)(brow + scol + q*4);
    }

    for (int ch = 0; ch < NC; ch++) {
        // stage current chunk (convert fp32 -> bf16 hi/lo)
        #pragma unroll
        for (int q = 0; q < 4; q++) {
            uint2 hi, lo;
            int idx = srow * SA + scol + q*4;
            split4(pa[q], hi, lo);
            *(uint2*)&Ah[idx] = hi;  *(uint2*)&Al[idx] = lo;
            split4(pb[q], hi, lo);
            *(uint2*)&Bh[idx] = hi;  *(uint2*)&Bl[idx] = lo;
        }
        __syncthreads();
        // prefetch next chunk into registers
        if (ch + 1 < NC) {
            const float* ap = arow + (ch+1)*KC + scol;
            const float* bp = brow + (ch+1)*KC + scol;
            #pragma unroll
            for (int q = 0; q < 4; q++) {
                pa[q] = *(const float4*)(ap + q*4);
                pb[q] = *(const float4*)(bp + q*4);
            }
        }
        // compute: 2 k16-steps, fragments via ldmatrix.x4
        #pragma unroll
        for (int ks = 0; ks < 2; ks++) {
            int kb = ks * 16;
            uint32_t bH[4][2], bL[4][2];
            #pragma unroll
            for (int p = 0; p < 2; p++) {
                uint32_t boffB = (uint32_t)(((b_row + p*16) * SA + kb + b_koff) * 2);
                ldmx4(bH[2*p][0], bH[2*p][1], bH[2*p+1][0], bH[2*p+1][1], BhAddr + boffB);
                ldmx4(bL[2*p][0], bL[2*p][1], bL[2*p+1][0], bL[2*p+1][1], BlAddr + boffB);
            }
            #pragma unroll
            for (int fi = 0; fi < 4; fi++) {
                uint32_t aoff = (uint32_t)(((a_row + fi*16) * SA + kb + a_koff) * 2);
                uint32_t aH[4], aL[4];
                ldmx4(aH[0], aH[1], aH[2], aH[3], AhAddr + aoff);
                ldmx4(aL[0], aL[1], aL[2], aL[3], AlAddr + aoff);
                #pragma unroll
                for (int nj = 0; nj < 4; nj++) mma16816(acc[fi][nj], aH, bH[nj]);
                #pragma unroll
                for (int nj = 0; nj < 4; nj++) mma16816(acc[fi][nj], aH, bL[nj]);
                #pragma unroll
                for (int nj = 0; nj < 4; nj++) mma16816(acc[fi][nj], aL, bH[nj]);
            }
        }
        __syncthreads();
    }

    // ---------------- epilogue ----------------
    #pragma unroll
    for (int fi = 0; fi < 4; fi++) {
        #pragma unroll
        for (int half = 0; half < 2; half++) {
            int rr = wm*64 + fi*16 + quad + half*8;
            if (rr >= cntRem) continue;
            int pos = off + m0 + rr;
            if (MODE == 0) {
                float* dst = g_h + (size_t)pos * NDIM + n0;
                const float* bp = bias + (size_t)e * NDIM + n0;
                #pragma unroll
                for (int nj = 0; nj < 4; nj++) {
                    int col = wn*32 + nj*8 + tq*2;
                    float x0 = acc[fi][nj][half*2+0] + bp[col];
                    float x1 = acc[fi][nj][half*2+1] + bp[col+1];
                    float2 o;
                    o.x = 0.5f * x0 * (1.0f + erff(x0 * 0.70710678118654752f));
                    o.y = 0.5f * x1 * (1.0f + erff(x1 * 0.70710678118654752f));
                    *(float2*)(dst + col) = o;
                }
            } else {
                int   tok = g_tok[pos];
                float p   = g_prob[pos];
                float* dst = outp + (size_t)tok * NDIM + n0;
                const float* bp = bias + (size_t)e * NDIM + n0;
                #pragma unroll
                for (int nj = 0; nj < 4; nj++) {
                    int col = wn*32 + nj*8 + tq*2;
                    atomicAdd(dst + col,     p * (acc[fi][nj][half*2+0] + bp[col]));
                    atomicAdd(dst + col + 1, p * (acc[fi][nj][half*2+1] + bp[col+1]));
                }
            }
        }
    }
}

// ---------------- launch ------------------------------------------------------
extern "C" void kernel_launch(void* const* d_in, const int* in_sizes, int n_in,
                              void* d_out, int out_size) {
    const float* z  = (const float*)d_in[0];
    const float* rw = (const float*)d_in[1];
    const float* rb = (const float*)d_in[2];
    const float* w1 = (const float*)d_in[3];
    const float* b1 = (const float*)d_in[4];
    const float* w2 = (const float*)d_in[5];
    const float* b2 = (const float*)d_in[6];
    float* out = (float*)d_out;

    init_kernel<<<1, 32>>>();
    router_kernel<<<N_TOK, 128>>>(z, rw, rb);
    scan_kernel<<<1, 32>>>();
    scatter_kernel<<<(N_TOK + 255) / 256, 256>>>();
    cudaMemsetAsync(out, 0, (size_t)N_TOK * OUTD * sizeof(float), 0);

    dim3 g1(HID / 128, (NPAIR + 127) / 128, NEXP);
    moe_gemm<DIM, HID, 0><<<g1, 256>>>(z, w1, b1, nullptr);
    dim3 g2(OUTD / 128, (NPAIR + 127) / 128, NEXP);
    moe_gemm<HID, OUTD, 1><<<g2, 256>>>(nullptr, w2, b2, out);
}